// round 11
// baseline (speedup 1.0000x reference)
#include <cuda_runtime.h>
#include <cuda.h>
#include <cstdint>

// SpikingLayer LIF scan, GB300 sm_103a — R8: TMA tensor stores for output.
// R7 showed DRAM pinned at ~78% independent of TMA read-box shape -> read
// supply is NOT the binder; the mixed 2:1 read/write stream with fine-grained
// (1 KB) STG writes is. Fix: stage 16 timesteps of spikes in smem and emit one
// 16 KB TMA tensor store per chunk (bulk_group, double-buffered) so DRAM sees
// large unidirectional bursts. 5 input stages (160 KB) + 2 output stages
// (32 KB) = 192 KB dyn smem. Scan math unchanged (single-rounded multiply
// decay == reference subtract form bitwise; __fmul_rn/__fadd_rn block FMA).

#define BATCH   32
#define TSTEPS  1024
#define NNEUR   1024
#define CTA_N   256
#define TCHUNK  16
#define ISTAGES 5
#define OSTAGES 2
#define NCHUNKS (TSTEPS / TCHUNK)                  // 64
#define ROWS_PER_CHUNK (TCHUNK * 2)                // 32
#define ISTAGE_FLOATS (ROWS_PER_CHUNK * CTA_N)     // 8192
#define ISTAGE_BYTES  (ISTAGE_FLOATS * 4)          // 32 KB
#define OSTAGE_FLOATS (TCHUNK * CTA_N)             // 4096
#define OSTAGE_BYTES  (OSTAGE_FLOATS * 4)          // 16 KB
#define DYN_SMEM (ISTAGES * ISTAGE_BYTES + OSTAGES * OSTAGE_BYTES)  // 192 KB

extern __shared__ __align__(1024) char smem_raw[];

// ------------- main kernel: TMA loads in, TMA tensor stores out -------------

__global__ void __launch_bounds__(CTA_N)
lif_scan_tmap2(const __grid_constant__ CUtensorMap tmap_in,
               const __grid_constant__ CUtensorMap tmap_out)
{
    __shared__ __align__(8) uint64_t mbar[ISTAGES];
    float* sdata = reinterpret_cast<float*>(smem_raw);
    float* odata = reinterpret_cast<float*>(smem_raw + ISTAGES * ISTAGE_BYTES);

    const int tid = threadIdx.x;
    const int nb  = blockIdx.x;     // neuron block 0..3
    const int b   = blockIdx.y;     // batch 0..31

    const uint32_t mb0 = (uint32_t)__cvta_generic_to_shared(&mbar[0]);
    const uint32_t sd0 = (uint32_t)__cvta_generic_to_shared(sdata);
    const uint32_t od0 = (uint32_t)__cvta_generic_to_shared(odata);
    const int x0     = nb * CTA_N;          // column coord (elements)
    const int ybase  = b * (TSTEPS * 2);    // first input row of this batch
    const int oybase = b * TSTEPS;          // first output row of this batch

    if (tid == 0) {
        #pragma unroll
        for (int s = 0; s < ISTAGES; s++)
            asm volatile("mbarrier.init.shared::cta.b64 [%0], 1;"
                         :: "r"(mb0 + s * 8) : "memory");
    }
    __syncthreads();

    // Prologue: fill all input stages.
    if (tid == 0) {
        #pragma unroll
        for (int c = 0; c < ISTAGES; c++) {
            const uint32_t mb = mb0 + c * 8;
            asm volatile("mbarrier.arrive.expect_tx.shared::cta.b64 _, [%0], %1;"
                         :: "r"(mb), "r"(ISTAGE_BYTES) : "memory");
            asm volatile(
                "cp.async.bulk.tensor.2d.shared::cta.global.tile"
                ".mbarrier::complete_tx::bytes [%0], [%1, {%2, %3}], [%4];"
                :: "r"(sd0 + c * ISTAGE_BYTES), "l"(&tmap_in),
                   "r"(x0), "r"(ybase + c * ROWS_PER_CHUNK), "r"(mb)
                : "memory");
        }
    }

    float i0 = 0.0f, i1 = 0.0f, v = 0.0f;

    #pragma unroll 1
    for (int c = 0; c < NCHUNKS; c++) {
        const int st = c % ISTAGES;
        const uint32_t ph = (uint32_t)(c / ISTAGES) & 1u;
        const uint32_t mb = mb0 + st * 8;

        uint32_t done = 0;
        while (!done) {
            asm volatile(
                "{\n\t.reg .pred p;\n\t"
                "mbarrier.try_wait.parity.acquire.cta.shared::cta.b64 p, [%1], %2, 0x989680;\n\t"
                "selp.b32 %0, 1, 0, p;\n\t}"
                : "=r"(done) : "r"(mb), "r"(ph) : "memory");
        }
        // Output buffer c&1 must be done being read by its previous TMA store
        // (chunk c-2). wait_group 1 keeps at most the newest store in flight.
        if (tid == 0)
            asm volatile("cp.async.bulk.wait_group 1;" ::: "memory");
        __syncthreads();

        const float* sf = sdata + st * ISTAGE_FLOATS;
        float*       of = odata + (c & 1) * OSTAGE_FLOATS;
        #pragma unroll
        for (int tl = 0; tl < TCHUNK; tl++) {
            const float a0 = sf[(tl * 2    ) * CTA_N + tid];
            const float a1 = sf[(tl * 2 + 1) * CTA_N + tid];
            i0 = __fadd_rn(__fmul_rn(i0, 0.75f),  a0);
            i1 = __fadd_rn(__fmul_rn(i1, 0.5f),   a1);
            v  = __fadd_rn(__fmul_rn(v,  0.875f), __fadd_rn(i0, i1));
            const float spk = (v >= 1.0f) ? 1.0f : 0.0f;
            v = __fadd_rn(v, -spk);
            of[tl * CTA_N + tid] = spk;
        }
        __syncthreads();   // input stage consumed; spike STS visible CTA-wide

        if (tid == 0) {
            const int cn = c + ISTAGES;
            if (cn < NCHUNKS) {
                asm volatile("mbarrier.arrive.expect_tx.shared::cta.b64 _, [%0], %1;"
                             :: "r"(mb), "r"(ISTAGE_BYTES) : "memory");
                asm volatile(
                    "cp.async.bulk.tensor.2d.shared::cta.global.tile"
                    ".mbarrier::complete_tx::bytes [%0], [%1, {%2, %3}], [%4];"
                    :: "r"(sd0 + st * ISTAGE_BYTES), "l"(&tmap_in),
                       "r"(x0), "r"(ybase + cn * ROWS_PER_CHUNK), "r"(mb)
                    : "memory");
            }
            // Generic-proxy smem writes -> async proxy, then bulk store.
            asm volatile("fence.proxy.async.shared::cta;" ::: "memory");
            asm volatile(
                "cp.async.bulk.tensor.2d.global.shared::cta.tile.bulk_group "
                "[%0, {%1, %2}], [%3];"
                :: "l"(&tmap_out), "r"(x0), "r"(oybase + c * TCHUNK),
                   "r"(od0 + (c & 1) * OSTAGE_BYTES)
                : "memory");
            asm volatile("cp.async.bulk.commit_group;" ::: "memory");
        }
    }

    if (tid == 0)
        asm volatile("cp.async.bulk.wait_group 0;" ::: "memory");
}

// ------------- fallback: TMA loads in, STG out (R7 path, known-correct) -------------

__global__ void __launch_bounds__(CTA_N)
lif_scan_tmap(const __grid_constant__ CUtensorMap tmap,
              float* __restrict__ out)
{
    __shared__ __align__(8) uint64_t mbar[ISTAGES];
    float* sdata = reinterpret_cast<float*>(smem_raw);

    const int tid = threadIdx.x;
    const int nb  = blockIdx.x;
    const int b   = blockIdx.y;

    float* pout = out + (b * TSTEPS) * NNEUR + nb * CTA_N + tid;

    const uint32_t mb0 = (uint32_t)__cvta_generic_to_shared(&mbar[0]);
    const uint32_t sd0 = (uint32_t)__cvta_generic_to_shared(sdata);
    const int x0 = nb * CTA_N;
    const int ybase = b * (TSTEPS * 2);

    if (tid == 0) {
        #pragma unroll
        for (int s = 0; s < ISTAGES; s++)
            asm volatile("mbarrier.init.shared::cta.b64 [%0], 1;"
                         :: "r"(mb0 + s * 8) : "memory");
    }
    __syncthreads();

    if (tid == 0) {
        #pragma unroll
        for (int c = 0; c < ISTAGES; c++) {
            const uint32_t mb = mb0 + c * 8;
            asm volatile("mbarrier.arrive.expect_tx.shared::cta.b64 _, [%0], %1;"
                         :: "r"(mb), "r"(ISTAGE_BYTES) : "memory");
            asm volatile(
                "cp.async.bulk.tensor.2d.shared::cta.global.tile"
                ".mbarrier::complete_tx::bytes [%0], [%1, {%2, %3}], [%4];"
                :: "r"(sd0 + c * ISTAGE_BYTES), "l"(&tmap),
                   "r"(x0), "r"(ybase + c * ROWS_PER_CHUNK), "r"(mb)
                : "memory");
        }
    }

    float i0 = 0.0f, i1 = 0.0f, v = 0.0f;

    #pragma unroll 1
    for (int c = 0; c < NCHUNKS; c++) {
        const int st = c % ISTAGES;
        const uint32_t ph = (uint32_t)(c / ISTAGES) & 1u;
        const uint32_t mb = mb0 + st * 8;

        uint32_t done = 0;
        while (!done) {
            asm volatile(
                "{\n\t.reg .pred p;\n\t"
                "mbarrier.try_wait.parity.acquire.cta.shared::cta.b64 p, [%1], %2, 0x989680;\n\t"
                "selp.b32 %0, 1, 0, p;\n\t}"
                : "=r"(done) : "r"(mb), "r"(ph) : "memory");
        }

        const float* sf = sdata + st * ISTAGE_FLOATS;
        #pragma unroll
        for (int tl = 0; tl < TCHUNK; tl++) {
            const float a0 = sf[(tl * 2    ) * CTA_N + tid];
            const float a1 = sf[(tl * 2 + 1) * CTA_N + tid];
            i0 = __fadd_rn(__fmul_rn(i0, 0.75f),  a0);
            i1 = __fadd_rn(__fmul_rn(i1, 0.5f),   a1);
            v  = __fadd_rn(__fmul_rn(v,  0.875f), __fadd_rn(i0, i1));
            const float spk = (v >= 1.0f) ? 1.0f : 0.0f;
            v = __fadd_rn(v, -spk);
            __stcs(pout + (c * TCHUNK + tl) * NNEUR, spk);
        }
        __syncthreads();

        const int cn = c + ISTAGES;
        if (tid == 0 && cn < NCHUNKS) {
            asm volatile("mbarrier.arrive.expect_tx.shared::cta.b64 _, [%0], %1;"
                         :: "r"(mb), "r"(ISTAGE_BYTES) : "memory");
            asm volatile(
                "cp.async.bulk.tensor.2d.shared::cta.global.tile"
                ".mbarrier::complete_tx::bytes [%0], [%1, {%2, %3}], [%4];"
                :: "r"(sd0 + st * ISTAGE_BYTES), "l"(&tmap),
                   "r"(x0), "r"(ybase + cn * ROWS_PER_CHUNK), "r"(mb)
                : "memory");
        }
    }
}

// ---------------- host ----------------

typedef CUresult (*PFN_encodeTiled)(
    CUtensorMap*, CUtensorMapDataType, cuuint32_t, void*,
    const cuuint64_t*, const cuuint64_t*, const cuuint32_t*, const cuuint32_t*,
    CUtensorMapInterleave, CUtensorMapSwizzle, CUtensorMapL2promotion,
    CUtensorMapFloatOOBfill);

static bool encode_2d(PFN_encodeTiled enc, CUtensorMap* tm, const void* ptr,
                      cuuint64_t h, cuuint32_t bw, cuuint32_t bh)
{
    cuuint64_t dims[2]    = {NNEUR, h};
    cuuint64_t strides[1] = {NNEUR * sizeof(float)};
    cuuint32_t box[2]     = {bw, bh};
    cuuint32_t estr[2]    = {1, 1};
    return enc(tm, CU_TENSOR_MAP_DATA_TYPE_FLOAT32, 2, (void*)ptr,
               dims, strides, box, estr,
               CU_TENSOR_MAP_INTERLEAVE_NONE, CU_TENSOR_MAP_SWIZZLE_NONE,
               CU_TENSOR_MAP_L2_PROMOTION_L2_128B,
               CU_TENSOR_MAP_FLOAT_OOB_FILL_NONE) == CUDA_SUCCESS;
}

extern "C" void kernel_launch(void* const* d_in, const int* in_sizes, int n_in,
                              void* d_out, int out_size)
{
    const float* in = (const float*)d_in[0];
    float* out = (float*)d_out;
    (void)in_sizes; (void)n_in; (void)out_size;

    dim3 block(CTA_N, 1, 1);
    dim3 grid(NNEUR / CTA_N, BATCH, 1);   // 4 x 32 = 128 CTAs

    PFN_encodeTiled encode = nullptr;
    cudaDriverEntryPointQueryResult qres = cudaDriverEntryPointSymbolNotFound;
    if (cudaGetDriverEntryPointByVersion("cuTensorMapEncodeTiled",
                                         (void**)&encode, 12000,
                                         cudaEnableDefault, &qres) != cudaSuccess
        || qres != cudaDriverEntryPointSuccess)
        encode = nullptr;

    CUtensorMap tin, tout;
    bool ok_in = false, ok_out = false;
    if (encode) {
        // Input 2D view: 1024 f32 wide, B*T*2 rows. Box 256 x 32 (32 KB).
        ok_in  = encode_2d(encode, &tin,  in,  (cuuint64_t)BATCH * TSTEPS * 2,
                           CTA_N, ROWS_PER_CHUNK);
        // Output 2D view: 1024 f32 wide, B*T rows. Box 256 x 16 (16 KB).
        ok_out = encode_2d(encode, &tout, out, (cuuint64_t)BATCH * TSTEPS,
                           CTA_N, TCHUNK);
    }

    if (ok_in && ok_out) {
        cudaFuncSetAttribute(lif_scan_tmap2,
                             cudaFuncAttributeMaxDynamicSharedMemorySize, DYN_SMEM);
        lif_scan_tmap2<<<grid, block, DYN_SMEM>>>(tin, tout);
    } else if (ok_in) {
        cudaFuncSetAttribute(lif_scan_tmap,
                             cudaFuncAttributeMaxDynamicSharedMemorySize, DYN_SMEM);
        lif_scan_tmap<<<grid, block, DYN_SMEM>>>(tin, out);
    }
    // (encode is available on all CUDA >= 12 runtimes on this image; if both
    // fail the bench will surface it as an empty capture -> loud failure.)
}

// round 12
// speedup vs baseline: 1.0478x; 1.0478x over previous
#include <cuda_runtime.h>
#include <cuda.h>
#include <cstdint>

// SpikingLayer LIF scan, GB300 sm_103a — R9: halve chunk count (TCHUNK 32).
// Evidence: 4 I/O architectures converge at ~57µs / ~79% DRAM = practical
// floor for this 2:1 r/w stream (7.05 TB/s effective). Remaining exposed cost
// is per-chunk sync (mbarrier wait + 2 BARs, ~64x). Fix: 32-timestep chunks:
// 2x fewer syncs, 64 KB read stages (2-deep ping-pong), 32 KB store bursts.
// Scan math unchanged (single-rounded multiply decay == reference subtract
// form bitwise; __fmul_rn/__fadd_rn block FMA contraction).

#define BATCH   32
#define TSTEPS  1024
#define NNEUR   1024
#define CTA_N   256
#define TCHUNK  32
#define ISTAGES 2
#define OSTAGES 2
#define NCHUNKS (TSTEPS / TCHUNK)                  // 32
#define ROWS_PER_CHUNK (TCHUNK * 2)                // 64
#define ISTAGE_FLOATS (ROWS_PER_CHUNK * CTA_N)     // 16384
#define ISTAGE_BYTES  (ISTAGE_FLOATS * 4)          // 64 KB
#define OSTAGE_FLOATS (TCHUNK * CTA_N)             // 8192
#define OSTAGE_BYTES  (OSTAGE_FLOATS * 4)          // 32 KB
#define DYN_SMEM (ISTAGES * ISTAGE_BYTES + OSTAGES * OSTAGE_BYTES)  // 192 KB

extern __shared__ __align__(1024) char smem_raw[];

// ------------- main kernel: TMA loads in, TMA tensor stores out -------------

__global__ void __launch_bounds__(CTA_N)
lif_scan_tmap2(const __grid_constant__ CUtensorMap tmap_in,
               const __grid_constant__ CUtensorMap tmap_out)
{
    __shared__ __align__(8) uint64_t mbar[ISTAGES];
    float* sdata = reinterpret_cast<float*>(smem_raw);
    float* odata = reinterpret_cast<float*>(smem_raw + ISTAGES * ISTAGE_BYTES);

    const int tid = threadIdx.x;
    const int nb  = blockIdx.x;     // neuron block 0..3
    const int b   = blockIdx.y;     // batch 0..31

    const uint32_t mb0 = (uint32_t)__cvta_generic_to_shared(&mbar[0]);
    const uint32_t sd0 = (uint32_t)__cvta_generic_to_shared(sdata);
    const uint32_t od0 = (uint32_t)__cvta_generic_to_shared(odata);
    const int x0     = nb * CTA_N;          // column coord (elements)
    const int ybase  = b * (TSTEPS * 2);    // first input row of this batch
    const int oybase = b * TSTEPS;          // first output row of this batch

    if (tid == 0) {
        #pragma unroll
        for (int s = 0; s < ISTAGES; s++)
            asm volatile("mbarrier.init.shared::cta.b64 [%0], 1;"
                         :: "r"(mb0 + s * 8) : "memory");
    }
    __syncthreads();

    // Prologue: fill both input stages.
    if (tid == 0) {
        #pragma unroll
        for (int c = 0; c < ISTAGES; c++) {
            const uint32_t mb = mb0 + c * 8;
            asm volatile("mbarrier.arrive.expect_tx.shared::cta.b64 _, [%0], %1;"
                         :: "r"(mb), "r"(ISTAGE_BYTES) : "memory");
            asm volatile(
                "cp.async.bulk.tensor.2d.shared::cta.global.tile"
                ".mbarrier::complete_tx::bytes [%0], [%1, {%2, %3}], [%4];"
                :: "r"(sd0 + c * ISTAGE_BYTES), "l"(&tmap_in),
                   "r"(x0), "r"(ybase + c * ROWS_PER_CHUNK), "r"(mb)
                : "memory");
        }
    }

    float i0 = 0.0f, i1 = 0.0f, v = 0.0f;

    #pragma unroll 1
    for (int c = 0; c < NCHUNKS; c++) {
        const int st = c & 1;
        const uint32_t ph = (uint32_t)(c >> 1) & 1u;
        const uint32_t mb = mb0 + st * 8;

        uint32_t done = 0;
        while (!done) {
            asm volatile(
                "{\n\t.reg .pred p;\n\t"
                "mbarrier.try_wait.parity.acquire.cta.shared::cta.b64 p, [%1], %2, 0x989680;\n\t"
                "selp.b32 %0, 1, 0, p;\n\t}"
                : "=r"(done) : "r"(mb), "r"(ph) : "memory");
        }
        // Output buffer c&1 must be drained by its previous TMA store (chunk
        // c-2); wait_group 1 keeps at most the newest store in flight.
        if (tid == 0)
            asm volatile("cp.async.bulk.wait_group 1;" ::: "memory");
        __syncthreads();

        const float* sf = sdata + st * ISTAGE_FLOATS;
        float*       of = odata + st * OSTAGE_FLOATS;
        #pragma unroll
        for (int tl = 0; tl < TCHUNK; tl++) {
            const float a0 = sf[(tl * 2    ) * CTA_N + tid];
            const float a1 = sf[(tl * 2 + 1) * CTA_N + tid];
            i0 = __fadd_rn(__fmul_rn(i0, 0.75f),  a0);
            i1 = __fadd_rn(__fmul_rn(i1, 0.5f),   a1);
            v  = __fadd_rn(__fmul_rn(v,  0.875f), __fadd_rn(i0, i1));
            const float spk = (v >= 1.0f) ? 1.0f : 0.0f;
            v = __fadd_rn(v, -spk);
            of[tl * CTA_N + tid] = spk;
        }
        __syncthreads();   // input stage consumed; spike STS visible CTA-wide

        if (tid == 0) {
            const int cn = c + ISTAGES;
            if (cn < NCHUNKS) {
                asm volatile("mbarrier.arrive.expect_tx.shared::cta.b64 _, [%0], %1;"
                             :: "r"(mb), "r"(ISTAGE_BYTES) : "memory");
                asm volatile(
                    "cp.async.bulk.tensor.2d.shared::cta.global.tile"
                    ".mbarrier::complete_tx::bytes [%0], [%1, {%2, %3}], [%4];"
                    :: "r"(sd0 + st * ISTAGE_BYTES), "l"(&tmap_in),
                       "r"(x0), "r"(ybase + cn * ROWS_PER_CHUNK), "r"(mb)
                    : "memory");
            }
            // Generic-proxy smem writes -> async proxy, then bulk store.
            asm volatile("fence.proxy.async.shared::cta;" ::: "memory");
            asm volatile(
                "cp.async.bulk.tensor.2d.global.shared::cta.tile.bulk_group "
                "[%0, {%1, %2}], [%3];"
                :: "l"(&tmap_out), "r"(x0), "r"(oybase + c * TCHUNK),
                   "r"(od0 + st * OSTAGE_BYTES)
                : "memory");
            asm volatile("cp.async.bulk.commit_group;" ::: "memory");
        }
    }

    if (tid == 0)
        asm volatile("cp.async.bulk.wait_group 0;" ::: "memory");
}

// ------------- fallback: TMA loads in, STG out (known-correct shape) -------------

__global__ void __launch_bounds__(CTA_N)
lif_scan_tmap(const __grid_constant__ CUtensorMap tmap,
              float* __restrict__ out)
{
    __shared__ __align__(8) uint64_t mbar[ISTAGES];
    float* sdata = reinterpret_cast<float*>(smem_raw);

    const int tid = threadIdx.x;
    const int nb  = blockIdx.x;
    const int b   = blockIdx.y;

    float* pout = out + (b * TSTEPS) * NNEUR + nb * CTA_N + tid;

    const uint32_t mb0 = (uint32_t)__cvta_generic_to_shared(&mbar[0]);
    const uint32_t sd0 = (uint32_t)__cvta_generic_to_shared(sdata);
    const int x0 = nb * CTA_N;
    const int ybase = b * (TSTEPS * 2);

    if (tid == 0) {
        #pragma unroll
        for (int s = 0; s < ISTAGES; s++)
            asm volatile("mbarrier.init.shared::cta.b64 [%0], 1;"
                         :: "r"(mb0 + s * 8) : "memory");
    }
    __syncthreads();

    if (tid == 0) {
        #pragma unroll
        for (int c = 0; c < ISTAGES; c++) {
            const uint32_t mb = mb0 + c * 8;
            asm volatile("mbarrier.arrive.expect_tx.shared::cta.b64 _, [%0], %1;"
                         :: "r"(mb), "r"(ISTAGE_BYTES) : "memory");
            asm volatile(
                "cp.async.bulk.tensor.2d.shared::cta.global.tile"
                ".mbarrier::complete_tx::bytes [%0], [%1, {%2, %3}], [%4];"
                :: "r"(sd0 + c * ISTAGE_BYTES), "l"(&tmap),
                   "r"(x0), "r"(ybase + c * ROWS_PER_CHUNK), "r"(mb)
                : "memory");
        }
    }

    float i0 = 0.0f, i1 = 0.0f, v = 0.0f;

    #pragma unroll 1
    for (int c = 0; c < NCHUNKS; c++) {
        const int st = c & 1;
        const uint32_t ph = (uint32_t)(c >> 1) & 1u;
        const uint32_t mb = mb0 + st * 8;

        uint32_t done = 0;
        while (!done) {
            asm volatile(
                "{\n\t.reg .pred p;\n\t"
                "mbarrier.try_wait.parity.acquire.cta.shared::cta.b64 p, [%1], %2, 0x989680;\n\t"
                "selp.b32 %0, 1, 0, p;\n\t}"
                : "=r"(done) : "r"(mb), "r"(ph) : "memory");
        }

        const float* sf = sdata + st * ISTAGE_FLOATS;
        #pragma unroll
        for (int tl = 0; tl < TCHUNK; tl++) {
            const float a0 = sf[(tl * 2    ) * CTA_N + tid];
            const float a1 = sf[(tl * 2 + 1) * CTA_N + tid];
            i0 = __fadd_rn(__fmul_rn(i0, 0.75f),  a0);
            i1 = __fadd_rn(__fmul_rn(i1, 0.5f),   a1);
            v  = __fadd_rn(__fmul_rn(v,  0.875f), __fadd_rn(i0, i1));
            const float spk = (v >= 1.0f) ? 1.0f : 0.0f;
            v = __fadd_rn(v, -spk);
            __stcs(pout + (c * TCHUNK + tl) * NNEUR, spk);
        }
        __syncthreads();

        const int cn = c + ISTAGES;
        if (tid == 0 && cn < NCHUNKS) {
            asm volatile("mbarrier.arrive.expect_tx.shared::cta.b64 _, [%0], %1;"
                         :: "r"(mb), "r"(ISTAGE_BYTES) : "memory");
            asm volatile(
                "cp.async.bulk.tensor.2d.shared::cta.global.tile"
                ".mbarrier::complete_tx::bytes [%0], [%1, {%2, %3}], [%4];"
                :: "r"(sd0 + st * ISTAGE_BYTES), "l"(&tmap),
                   "r"(x0), "r"(ybase + cn * ROWS_PER_CHUNK), "r"(mb)
                : "memory");
        }
    }
}

// ---------------- host ----------------

typedef CUresult (*PFN_encodeTiled)(
    CUtensorMap*, CUtensorMapDataType, cuuint32_t, void*,
    const cuuint64_t*, const cuuint64_t*, const cuuint32_t*, const cuuint32_t*,
    CUtensorMapInterleave, CUtensorMapSwizzle, CUtensorMapL2promotion,
    CUtensorMapFloatOOBfill);

static bool encode_2d(PFN_encodeTiled enc, CUtensorMap* tm, const void* ptr,
                      cuuint64_t h, cuuint32_t bw, cuuint32_t bh)
{
    cuuint64_t dims[2]    = {NNEUR, h};
    cuuint64_t strides[1] = {NNEUR * sizeof(float)};
    cuuint32_t box[2]     = {bw, bh};
    cuuint32_t estr[2]    = {1, 1};
    return enc(tm, CU_TENSOR_MAP_DATA_TYPE_FLOAT32, 2, (void*)ptr,
               dims, strides, box, estr,
               CU_TENSOR_MAP_INTERLEAVE_NONE, CU_TENSOR_MAP_SWIZZLE_NONE,
               CU_TENSOR_MAP_L2_PROMOTION_L2_128B,
               CU_TENSOR_MAP_FLOAT_OOB_FILL_NONE) == CUDA_SUCCESS;
}

extern "C" void kernel_launch(void* const* d_in, const int* in_sizes, int n_in,
                              void* d_out, int out_size)
{
    const float* in = (const float*)d_in[0];
    float* out = (float*)d_out;
    (void)in_sizes; (void)n_in; (void)out_size;

    dim3 block(CTA_N, 1, 1);
    dim3 grid(NNEUR / CTA_N, BATCH, 1);   // 4 x 32 = 128 CTAs

    PFN_encodeTiled encode = nullptr;
    cudaDriverEntryPointQueryResult qres = cudaDriverEntryPointSymbolNotFound;
    if (cudaGetDriverEntryPointByVersion("cuTensorMapEncodeTiled",
                                         (void**)&encode, 12000,
                                         cudaEnableDefault, &qres) != cudaSuccess
        || qres != cudaDriverEntryPointSuccess)
        encode = nullptr;

    CUtensorMap tin, tout;
    bool ok_in = false, ok_out = false;
    if (encode) {
        // Input 2D view: 1024 f32 wide, B*T*2 rows. Box 256 x 64 (64 KB).
        ok_in  = encode_2d(encode, &tin,  in,  (cuuint64_t)BATCH * TSTEPS * 2,
                           CTA_N, ROWS_PER_CHUNK);
        // Output 2D view: 1024 f32 wide, B*T rows. Box 256 x 32 (32 KB).
        ok_out = encode_2d(encode, &tout, out, (cuuint64_t)BATCH * TSTEPS,
                           CTA_N, TCHUNK);
    }

    if (ok_in && ok_out) {
        cudaFuncSetAttribute(lif_scan_tmap2,
                             cudaFuncAttributeMaxDynamicSharedMemorySize, DYN_SMEM);
        lif_scan_tmap2<<<grid, block, DYN_SMEM>>>(tin, tout);
    } else if (ok_in) {
        cudaFuncSetAttribute(lif_scan_tmap,
                             cudaFuncAttributeMaxDynamicSharedMemorySize, DYN_SMEM);
        lif_scan_tmap<<<grid, block, DYN_SMEM>>>(tin, out);
    }
}

// round 13
// speedup vs baseline: 1.0520x; 1.0040x over previous
#include <cuda_runtime.h>
#include <cuda.h>
#include <cstdint>

// SpikingLayer LIF scan, GB300 sm_103a — R10: engage all 148 SMs.
// R9 equilibrium: 81% DRAM, 7.2 TB/s requested, with only 128/148 SMs active.
// Request generation is per-SM; R6-vs-R7 showed 512B vs 1KB TMA rows is
// neutral, so CTA_N=128 is free on the read path. Grid 8x32 = 256 CTAs ->
// all SMs active, 2x independent streams. Per-CTA: TCHUNK=32, 2x32KB input
// ping-pong + 2x16KB output buffers = 96 KB (2 CTAs/SM). Scan math unchanged
// (single-rounded multiply decay == reference subtract form bitwise;
// __fmul_rn/__fadd_rn block FMA contraction).

#define BATCH   32
#define TSTEPS  1024
#define NNEUR   1024
#define CTA_N   128
#define TCHUNK  32
#define ISTAGES 2
#define OSTAGES 2
#define NCHUNKS (TSTEPS / TCHUNK)                  // 32
#define ROWS_PER_CHUNK (TCHUNK * 2)                // 64
#define ISTAGE_FLOATS (ROWS_PER_CHUNK * CTA_N)     // 8192
#define ISTAGE_BYTES  (ISTAGE_FLOATS * 4)          // 32 KB
#define OSTAGE_FLOATS (TCHUNK * CTA_N)             // 4096
#define OSTAGE_BYTES  (OSTAGE_FLOATS * 4)          // 16 KB
#define DYN_SMEM (ISTAGES * ISTAGE_BYTES + OSTAGES * OSTAGE_BYTES)  // 96 KB

extern __shared__ __align__(1024) char smem_raw[];

// ------------- main kernel: TMA loads in, TMA tensor stores out -------------

__global__ void __launch_bounds__(CTA_N)
lif_scan_tmap2(const __grid_constant__ CUtensorMap tmap_in,
               const __grid_constant__ CUtensorMap tmap_out)
{
    __shared__ __align__(8) uint64_t mbar[ISTAGES];
    float* sdata = reinterpret_cast<float*>(smem_raw);
    float* odata = reinterpret_cast<float*>(smem_raw + ISTAGES * ISTAGE_BYTES);

    const int tid = threadIdx.x;
    const int nb  = blockIdx.x;     // neuron block 0..7
    const int b   = blockIdx.y;     // batch 0..31

    const uint32_t mb0 = (uint32_t)__cvta_generic_to_shared(&mbar[0]);
    const uint32_t sd0 = (uint32_t)__cvta_generic_to_shared(sdata);
    const uint32_t od0 = (uint32_t)__cvta_generic_to_shared(odata);
    const int x0     = nb * CTA_N;          // column coord (elements)
    const int ybase  = b * (TSTEPS * 2);    // first input row of this batch
    const int oybase = b * TSTEPS;          // first output row of this batch

    if (tid == 0) {
        #pragma unroll
        for (int s = 0; s < ISTAGES; s++)
            asm volatile("mbarrier.init.shared::cta.b64 [%0], 1;"
                         :: "r"(mb0 + s * 8) : "memory");
    }
    __syncthreads();

    // Prologue: fill both input stages.
    if (tid == 0) {
        #pragma unroll
        for (int c = 0; c < ISTAGES; c++) {
            const uint32_t mb = mb0 + c * 8;
            asm volatile("mbarrier.arrive.expect_tx.shared::cta.b64 _, [%0], %1;"
                         :: "r"(mb), "r"(ISTAGE_BYTES) : "memory");
            asm volatile(
                "cp.async.bulk.tensor.2d.shared::cta.global.tile"
                ".mbarrier::complete_tx::bytes [%0], [%1, {%2, %3}], [%4];"
                :: "r"(sd0 + c * ISTAGE_BYTES), "l"(&tmap_in),
                   "r"(x0), "r"(ybase + c * ROWS_PER_CHUNK), "r"(mb)
                : "memory");
        }
    }

    float i0 = 0.0f, i1 = 0.0f, v = 0.0f;

    #pragma unroll 1
    for (int c = 0; c < NCHUNKS; c++) {
        const int st = c & 1;
        const uint32_t ph = (uint32_t)(c >> 1) & 1u;
        const uint32_t mb = mb0 + st * 8;

        uint32_t done = 0;
        while (!done) {
            asm volatile(
                "{\n\t.reg .pred p;\n\t"
                "mbarrier.try_wait.parity.acquire.cta.shared::cta.b64 p, [%1], %2, 0x989680;\n\t"
                "selp.b32 %0, 1, 0, p;\n\t}"
                : "=r"(done) : "r"(mb), "r"(ph) : "memory");
        }
        // Output buffer st must be drained by its previous TMA store (chunk
        // c-2); wait_group 1 keeps at most the newest store in flight.
        if (tid == 0)
            asm volatile("cp.async.bulk.wait_group 1;" ::: "memory");
        __syncthreads();

        const float* sf = sdata + st * ISTAGE_FLOATS;
        float*       of = odata + st * OSTAGE_FLOATS;
        #pragma unroll
        for (int tl = 0; tl < TCHUNK; tl++) {
            const float a0 = sf[(tl * 2    ) * CTA_N + tid];
            const float a1 = sf[(tl * 2 + 1) * CTA_N + tid];
            i0 = __fadd_rn(__fmul_rn(i0, 0.75f),  a0);
            i1 = __fadd_rn(__fmul_rn(i1, 0.5f),   a1);
            v  = __fadd_rn(__fmul_rn(v,  0.875f), __fadd_rn(i0, i1));
            const float spk = (v >= 1.0f) ? 1.0f : 0.0f;
            v = __fadd_rn(v, -spk);
            of[tl * CTA_N + tid] = spk;
        }
        __syncthreads();   // input stage consumed; spike STS visible CTA-wide

        if (tid == 0) {
            const int cn = c + ISTAGES;
            if (cn < NCHUNKS) {
                asm volatile("mbarrier.arrive.expect_tx.shared::cta.b64 _, [%0], %1;"
                             :: "r"(mb), "r"(ISTAGE_BYTES) : "memory");
                asm volatile(
                    "cp.async.bulk.tensor.2d.shared::cta.global.tile"
                    ".mbarrier::complete_tx::bytes [%0], [%1, {%2, %3}], [%4];"
                    :: "r"(sd0 + st * ISTAGE_BYTES), "l"(&tmap_in),
                       "r"(x0), "r"(ybase + cn * ROWS_PER_CHUNK), "r"(mb)
                    : "memory");
            }
            // Generic-proxy smem writes -> async proxy, then bulk store.
            asm volatile("fence.proxy.async.shared::cta;" ::: "memory");
            asm volatile(
                "cp.async.bulk.tensor.2d.global.shared::cta.tile.bulk_group "
                "[%0, {%1, %2}], [%3];"
                :: "l"(&tmap_out), "r"(x0), "r"(oybase + c * TCHUNK),
                   "r"(od0 + st * OSTAGE_BYTES)
                : "memory");
            asm volatile("cp.async.bulk.commit_group;" ::: "memory");
        }
    }

    if (tid == 0)
        asm volatile("cp.async.bulk.wait_group 0;" ::: "memory");
}

// ------------- fallback: TMA loads in, STG out (known-correct shape) -------------

__global__ void __launch_bounds__(CTA_N)
lif_scan_tmap(const __grid_constant__ CUtensorMap tmap,
              float* __restrict__ out)
{
    __shared__ __align__(8) uint64_t mbar[ISTAGES];
    float* sdata = reinterpret_cast<float*>(smem_raw);

    const int tid = threadIdx.x;
    const int nb  = blockIdx.x;
    const int b   = blockIdx.y;

    float* pout = out + (b * TSTEPS) * NNEUR + nb * CTA_N + tid;

    const uint32_t mb0 = (uint32_t)__cvta_generic_to_shared(&mbar[0]);
    const uint32_t sd0 = (uint32_t)__cvta_generic_to_shared(sdata);
    const int x0 = nb * CTA_N;
    const int ybase = b * (TSTEPS * 2);

    if (tid == 0) {
        #pragma unroll
        for (int s = 0; s < ISTAGES; s++)
            asm volatile("mbarrier.init.shared::cta.b64 [%0], 1;"
                         :: "r"(mb0 + s * 8) : "memory");
    }
    __syncthreads();

    if (tid == 0) {
        #pragma unroll
        for (int c = 0; c < ISTAGES; c++) {
            const uint32_t mb = mb0 + c * 8;
            asm volatile("mbarrier.arrive.expect_tx.shared::cta.b64 _, [%0], %1;"
                         :: "r"(mb), "r"(ISTAGE_BYTES) : "memory");
            asm volatile(
                "cp.async.bulk.tensor.2d.shared::cta.global.tile"
                ".mbarrier::complete_tx::bytes [%0], [%1, {%2, %3}], [%4];"
                :: "r"(sd0 + c * ISTAGE_BYTES), "l"(&tmap),
                   "r"(x0), "r"(ybase + c * ROWS_PER_CHUNK), "r"(mb)
                : "memory");
        }
    }

    float i0 = 0.0f, i1 = 0.0f, v = 0.0f;

    #pragma unroll 1
    for (int c = 0; c < NCHUNKS; c++) {
        const int st = c & 1;
        const uint32_t ph = (uint32_t)(c >> 1) & 1u;
        const uint32_t mb = mb0 + st * 8;

        uint32_t done = 0;
        while (!done) {
            asm volatile(
                "{\n\t.reg .pred p;\n\t"
                "mbarrier.try_wait.parity.acquire.cta.shared::cta.b64 p, [%1], %2, 0x989680;\n\t"
                "selp.b32 %0, 1, 0, p;\n\t}"
                : "=r"(done) : "r"(mb), "r"(ph) : "memory");
        }

        const float* sf = sdata + st * ISTAGE_FLOATS;
        #pragma unroll
        for (int tl = 0; tl < TCHUNK; tl++) {
            const float a0 = sf[(tl * 2    ) * CTA_N + tid];
            const float a1 = sf[(tl * 2 + 1) * CTA_N + tid];
            i0 = __fadd_rn(__fmul_rn(i0, 0.75f),  a0);
            i1 = __fadd_rn(__fmul_rn(i1, 0.5f),   a1);
            v  = __fadd_rn(__fmul_rn(v,  0.875f), __fadd_rn(i0, i1));
            const float spk = (v >= 1.0f) ? 1.0f : 0.0f;
            v = __fadd_rn(v, -spk);
            __stcs(pout + (c * TCHUNK + tl) * NNEUR, spk);
        }
        __syncthreads();

        const int cn = c + ISTAGES;
        if (tid == 0 && cn < NCHUNKS) {
            asm volatile("mbarrier.arrive.expect_tx.shared::cta.b64 _, [%0], %1;"
                         :: "r"(mb), "r"(ISTAGE_BYTES) : "memory");
            asm volatile(
                "cp.async.bulk.tensor.2d.shared::cta.global.tile"
                ".mbarrier::complete_tx::bytes [%0], [%1, {%2, %3}], [%4];"
                :: "r"(sd0 + st * ISTAGE_BYTES), "l"(&tmap),
                   "r"(x0), "r"(ybase + cn * ROWS_PER_CHUNK), "r"(mb)
                : "memory");
        }
    }
}

// ---------------- host ----------------

typedef CUresult (*PFN_encodeTiled)(
    CUtensorMap*, CUtensorMapDataType, cuuint32_t, void*,
    const cuuint64_t*, const cuuint64_t*, const cuuint32_t*, const cuuint32_t*,
    CUtensorMapInterleave, CUtensorMapSwizzle, CUtensorMapL2promotion,
    CUtensorMapFloatOOBfill);

static bool encode_2d(PFN_encodeTiled enc, CUtensorMap* tm, const void* ptr,
                      cuuint64_t h, cuuint32_t bw, cuuint32_t bh)
{
    cuuint64_t dims[2]    = {NNEUR, h};
    cuuint64_t strides[1] = {NNEUR * sizeof(float)};
    cuuint32_t box[2]     = {bw, bh};
    cuuint32_t estr[2]    = {1, 1};
    return enc(tm, CU_TENSOR_MAP_DATA_TYPE_FLOAT32, 2, (void*)ptr,
               dims, strides, box, estr,
               CU_TENSOR_MAP_INTERLEAVE_NONE, CU_TENSOR_MAP_SWIZZLE_NONE,
               CU_TENSOR_MAP_L2_PROMOTION_L2_128B,
               CU_TENSOR_MAP_FLOAT_OOB_FILL_NONE) == CUDA_SUCCESS;
}

extern "C" void kernel_launch(void* const* d_in, const int* in_sizes, int n_in,
                              void* d_out, int out_size)
{
    const float* in = (const float*)d_in[0];
    float* out = (float*)d_out;
    (void)in_sizes; (void)n_in; (void)out_size;

    dim3 block(CTA_N, 1, 1);
    dim3 grid(NNEUR / CTA_N, BATCH, 1);   // 8 x 32 = 256 CTAs, all SMs active

    PFN_encodeTiled encode = nullptr;
    cudaDriverEntryPointQueryResult qres = cudaDriverEntryPointSymbolNotFound;
    if (cudaGetDriverEntryPointByVersion("cuTensorMapEncodeTiled",
                                         (void**)&encode, 12000,
                                         cudaEnableDefault, &qres) != cudaSuccess
        || qres != cudaDriverEntryPointSuccess)
        encode = nullptr;

    CUtensorMap tin, tout;
    bool ok_in = false, ok_out = false;
    if (encode) {
        // Input 2D view: 1024 f32 wide, B*T*2 rows. Box 128 x 64 (32 KB).
        ok_in  = encode_2d(encode, &tin,  in,  (cuuint64_t)BATCH * TSTEPS * 2,
                           CTA_N, ROWS_PER_CHUNK);
        // Output 2D view: 1024 f32 wide, B*T rows. Box 128 x 32 (16 KB).
        ok_out = encode_2d(encode, &tout, out, (cuuint64_t)BATCH * TSTEPS,
                           CTA_N, TCHUNK);
    }

    if (ok_in && ok_out) {
        cudaFuncSetAttribute(lif_scan_tmap2,
                             cudaFuncAttributeMaxDynamicSharedMemorySize, DYN_SMEM);
        lif_scan_tmap2<<<grid, block, DYN_SMEM>>>(tin, tout);
    } else if (ok_in) {
        cudaFuncSetAttribute(lif_scan_tmap,
                             cudaFuncAttributeMaxDynamicSharedMemorySize, DYN_SMEM);
        lif_scan_tmap<<<grid, block, DYN_SMEM>>>(tin, out);
    }
}